// round 16
// baseline (speedup 1.0000x reference)
#include <cuda_runtime.h>

// FullAutoLSTM, GB300 sm_103a — 2-D tiled persistent kernel, grid barrier,
// folded autoregressive feedback.
// 256 CTAs = 32 row-tiles (32 batch rows) x 8 unit-tiles (32 hidden units),
// 256 threads, 2 CTAs/SM. Weight slice 147KB/CTA read once per step (L1-heavy).
// y feedback folded into W_hh' = W_hh + W_out @ W_ih[24:32] (exact algebra);
// y output computed as an extra fused column inside the GEMM.
// c in registers; h via L2 double buffer + per-step sense barrier.

typedef unsigned long long ull;

#define TW   512
#define TT   1024
#define NH   256
#define NO   8
#define NK   288      // 32 input slots + 256 hidden
#define NR   32       // batch rows per CTA
#define NCTA 256      // 32 rtiles x 8 utiles
#define THREADS 256
#define SPAIR 18      // float2 stride per k row (144B, even -> LDS.128 legal)
#define SMEM_BYTES (NK * SPAIR * 8 + NH * NO * 4)   // 41472 + 8192 = 49664

// Weights [phase][utile][k][l*4+gate]; gate order i,f,g,o; col = gate*256+u.
__device__ float g_W[2 * 8 * NK * 128];
__device__ float g_b2[2 * 1024];          // [phase][col]
__device__ float g_hbuf[2][1024 * NH];
__device__ unsigned g_barctr;
__device__ volatile unsigned g_barsense;

__device__ __forceinline__ void fma2(ull& a, ull x, ull w) {
    asm("fma.rn.f32x2 %0, %1, %2, %0;" : "+l"(a) : "l"(x), "l"(w));
}
__device__ __forceinline__ ull dup2(float v) {
    ull r; asm("mov.b64 %0, {%1, %1};" : "=l"(r) : "f"(v)); return r;
}
__device__ __forceinline__ float2 unp(ull v) {
    float2 r; asm("mov.b64 {%0, %1}, %2;" : "=f"(r.x), "=f"(r.y) : "l"(v)); return r;
}
__device__ __forceinline__ float fsig(float x) { return 1.0f / (1.0f + __expf(-x)); }
__device__ __forceinline__ float fth(float x)  { return 2.0f / (1.0f + __expf(-2.0f * x)) - 1.0f; }

__global__ void repack_kernel(const float* __restrict__ W_ih,
                              const float* __restrict__ W_hh,
                              const float* __restrict__ W_out) {
    int i = blockIdx.x * blockDim.x + threadIdx.x;
    if (i >= 2 * 8 * NK * 128) return;
    int gate = i & 3;
    int l    = (i >> 2) & 31;
    int k    = (i >> 7) % NK;
    int pu   = i / (NK * 128);
    int ut   = pu & 7;
    int ph   = pu >> 3;
    int col  = gate * 256 + ut * 32 + l;
    float v;
    if (k < 32) {
        v = (ph == 0 || k < 24) ? W_ih[(size_t)k * 1024 + col] : 0.0f;
    } else {
        v = W_hh[(size_t)(k - 32) * 1024 + col];
        if (ph == 1) {
            float a = 0.0f;
#pragma unroll
            for (int o = 0; o < 8; o++)
                a += W_out[(k - 32) * 8 + o] * W_ih[(size_t)(24 + o) * 1024 + col];
            v += a;
        }
    }
    g_W[i] = v;
}

__global__ void bias_kernel(const float* __restrict__ W_ih,
                            const float* __restrict__ b,
                            const float* __restrict__ b_out) {
    int i = blockIdx.x * blockDim.x + threadIdx.x;
    if (i == 0) { g_barctr = 0; g_barsense = 0; }
    if (i >= 2048) return;
    int ph = i >> 10, col = i & 1023;
    float v = b[col];
    if (ph) {
#pragma unroll
        for (int o = 0; o < 8; o++)
            v += b_out[o] * W_ih[(size_t)(24 + o) * 1024 + col];
    }
    g_b2[i] = v;
}

// Stage h (32 rows x 256 units) into x-tile rows [32,288) as pairs {r, r+16}.
__device__ __forceinline__ void stage_h(float2* sx, const float* __restrict__ hsrc,
                                        int r0, int wq, int e) {
#pragma unroll
    for (int jj = 0; jj < 2; jj++) {
        int p = wq + 8 * jj;
        const float* rowA = hsrc + (size_t)(r0 + p) * NH;
        const float* rowB = hsrc + (size_t)(r0 + p + 16) * NH;
#pragma unroll
        for (int ii = 0; ii < 8; ii++) {
            int u = 32 * ii + e;
            sx[(32 + u) * SPAIR + p] = make_float2(rowA[u], rowB[u]);
        }
    }
}

__global__ void __launch_bounds__(THREADS, 2)
lstm_main(const float* __restrict__ c0, const float* __restrict__ h0,
          const float* __restrict__ warm,    // (B, 512, 32)
          const float* __restrict__ autoin,  // (B, 512, 24)
          const float* __restrict__ W_out,   // (256, 8)
          const float* __restrict__ b_out,   // (8)
          float* __restrict__ out)           // (B, 1024, 8)
{
    extern __shared__ float2 sx[];                    // [NK][SPAIR]
    float* swout = (float*)(sx + NK * SPAIR);         // [256][8]

    const int t  = threadIdx.x;
    const int l  = t >> 3;          // unit 0..31
    const int g  = t & 7;           // row-group
    const int wq = t >> 5;          // warp
    const int e  = t & 31;          // lane
    const int ut = blockIdx.x & 7;
    const int r0 = (blockIdx.x >> 3) * NR;
    const int U  = ut * 32 + l;     // global hidden unit

    for (int i = t; i < NH * NO; i += THREADS) swout[i] = W_out[i];

    // Gate biases for both phases (i,f,g,o).
    float bw[4], ba[4];
#pragma unroll
    for (int q = 0; q < 4; q++) {
        bw[q] = g_b2[q * 256 + U];
        ba[q] = g_b2[1024 + q * 256 + U];
    }

    // Rows owned by this thread: pair P0={2g,2g+16}, P1={2g+1,2g+17}.
    float cr[4];
    cr[0] = c0[(size_t)(r0 + 2 * g)      * NH + U];
    cr[1] = c0[(size_t)(r0 + 2 * g + 16) * NH + U];
    cr[2] = c0[(size_t)(r0 + 2 * g + 1)  * NH + U];
    cr[3] = c0[(size_t)(r0 + 2 * g + 17) * NH + U];

    const float4* __restrict__ wpW =
        reinterpret_cast<const float4*>(g_W) + (size_t)ut * NK * 32 + l;
    const float4* __restrict__ wpA = wpW + (size_t)8 * NK * 32;

    // y fused-column assignment (threads 0..127): o = t>>4, pair = 2g + bit3.
    const bool doy = (t < 128);
    const int  yo   = t >> 4;
    const int  pbit = (t >> 3) & 1;
    const float bor = doy ? b_out[yo] : 0.0f;

    for (int s = 0; s < TT; s++) {
        // ---- stage h_{s-1} and x_s ----
        stage_h(sx, (s == 0) ? h0 : g_hbuf[s & 1], r0, wq, e);
        if (s < TW) {
#pragma unroll
            for (int jj = 0; jj < 2; jj++) {
                int p = wq + 8 * jj;
                const float* xA = warm + ((size_t)(r0 + p) * TW + s) * 32;
                const float* xB = warm + ((size_t)(r0 + p + 16) * TW + s) * 32;
                sx[e * SPAIR + p] = make_float2(xA[e], xB[e]);
            }
        } else {
#pragma unroll
            for (int jj = 0; jj < 2; jj++) {
                int p = wq + 8 * jj;
                const float* xA = autoin + ((size_t)(r0 + p) * TW + (s - TW)) * 24;
                const float* xB = autoin + ((size_t)(r0 + p + 16) * TW + (s - TW)) * 24;
                float va = (e < 24) ? xA[e] : 0.0f;   // slots [24,32) = 0 (folded)
                float vb = (e < 24) ? xB[e] : 0.0f;
                sx[e * SPAIR + p] = make_float2(va, vb);
            }
        }
        __syncthreads();

        const float4* __restrict__ wp = (s < TW) ? wpW : wpA;

        // ---- z GEMM (+ fused y_{s-1} column) ----
        ull a00 = 0, a01 = 0, a02 = 0, a03 = 0;
        ull a10 = 0, a11 = 0, a12 = 0, a13 = 0;
        ull yacc = 0;

#pragma unroll 4
        for (int k = 0; k < 32; k++) {
            float4 w4 = __ldg(&wp[(size_t)k * 32]);
            ulonglong2 xp2 = *(const ulonglong2*)&sx[k * SPAIR + 2 * g];
            ull wi = dup2(w4.x), wf = dup2(w4.y), wg = dup2(w4.z), wo = dup2(w4.w);
            fma2(a00, xp2.x, wi); fma2(a01, xp2.x, wf);
            fma2(a02, xp2.x, wg); fma2(a03, xp2.x, wo);
            fma2(a10, xp2.y, wi); fma2(a11, xp2.y, wf);
            fma2(a12, xp2.y, wg); fma2(a13, xp2.y, wo);
        }
#pragma unroll 4
        for (int k = 32; k < NK; k++) {
            float4 w4 = __ldg(&wp[(size_t)k * 32]);
            ulonglong2 xp2 = *(const ulonglong2*)&sx[k * SPAIR + 2 * g];
            ull wi = dup2(w4.x), wf = dup2(w4.y), wg = dup2(w4.z), wo = dup2(w4.w);
            fma2(a00, xp2.x, wi); fma2(a01, xp2.x, wf);
            fma2(a02, xp2.x, wg); fma2(a03, xp2.x, wo);
            fma2(a10, xp2.y, wi); fma2(a11, xp2.y, wf);
            fma2(a12, xp2.y, wg); fma2(a13, xp2.y, wo);
            if (doy) {
                ull xp = pbit ? xp2.y : xp2.x;
                fma2(yacc, xp, dup2(swout[(k - 32) * 8 + yo]));
            }
        }

        // ---- y_{s-1} output (unit-tile 0 writes; computed by all for balance)
        if (doy && ut == 0 && s >= 1) {
            float2 yv = unp(yacc);
            int p = 2 * g + pbit;
            out[((size_t)(r0 + p)      * TT + (s - 1)) * NO + yo] = yv.x + bor;
            out[((size_t)(r0 + p + 16) * TT + (s - 1)) * NO + yo] = yv.y + bor;
        }

        // ---- gates + cell update ----
        const float bb0 = (s < TW) ? bw[0] : ba[0];
        const float bb1 = (s < TW) ? bw[1] : ba[1];
        const float bb2 = (s < TW) ? bw[2] : ba[2];
        const float bb3 = (s < TW) ? bw[3] : ba[3];
        float2 zi0 = unp(a00), zf0 = unp(a01), zg0 = unp(a02), zo0 = unp(a03);
        float2 zi1 = unp(a10), zf1 = unp(a11), zg1 = unp(a12), zo1 = unp(a13);
        float zi[4] = {zi0.x, zi0.y, zi1.x, zi1.y};
        float zf[4] = {zf0.x, zf0.y, zf1.x, zf1.y};
        float zg[4] = {zg0.x, zg0.y, zg1.x, zg1.y};
        float zo[4] = {zo0.x, zo0.y, zo1.x, zo1.y};
        float hv[4];
#pragma unroll
        for (int q = 0; q < 4; q++) {
            float ig = fsig(zi[q] + bb0);
            float fg = fsig(zf[q] + bb1);
            float gg = fth(zg[q] + bb2);
            float og = fsig(zo[q] + bb3);
            float c  = fmaf(fg, cr[q], ig * gg);
            cr[q] = c;
            hv[q] = og * fth(c);
        }
        // rows for q: {2g, 2g+16, 2g+1, 2g+17}
        {
            float* hd = g_hbuf[(s + 1) & 1];
            hd[(size_t)(r0 + 2 * g)      * NH + U] = hv[0];
            hd[(size_t)(r0 + 2 * g + 16) * NH + U] = hv[1];
            hd[(size_t)(r0 + 2 * g + 1)  * NH + U] = hv[2];
            hd[(size_t)(r0 + 2 * g + 17) * NH + U] = hv[3];
        }

        // ---- grid barrier ----
        __syncthreads();
        if (t == 0) {
            __threadfence();
            unsigned tgt = (unsigned)(s + 1);
            if (atomicAdd(&g_barctr, 1) == NCTA - 1) {
                g_barctr = 0;
                __threadfence();
                g_barsense = tgt;
            } else {
                while (g_barsense < tgt) { }
            }
            __threadfence();
        }
        __syncthreads();
    }

    // ---- tail: y_1023 from h_1023 (unit-tile 0 CTAs only) ----
    if (ut == 0) {
        stage_h(sx, g_hbuf[TT & 1], r0, wq, e);
        __syncthreads();
        if (doy) {
            ull yacc = 0;
#pragma unroll 8
            for (int k = 32; k < NK; k++) {
                ulonglong2 xp2 = *(const ulonglong2*)&sx[k * SPAIR + 2 * g];
                ull xp = pbit ? xp2.y : xp2.x;
                fma2(yacc, xp, dup2(swout[(k - 32) * 8 + yo]));
            }
            float2 yv = unp(yacc);
            int p = 2 * g + pbit;
            out[((size_t)(r0 + p)      * TT + (TT - 1)) * NO + yo] = yv.x + bor;
            out[((size_t)(r0 + p + 16) * TT + (TT - 1)) * NO + yo] = yv.y + bor;
        }
    }
}

extern "C" void kernel_launch(void* const* d_in, const int* in_sizes, int n_in,
                              void* d_out, int out_size) {
    const float* c0     = (const float*)d_in[0];
    const float* h0     = (const float*)d_in[1];
    const float* warm   = (const float*)d_in[2];
    const float* autoin = (const float*)d_in[3];
    const float* W_ih   = (const float*)d_in[4];
    const float* W_hh   = (const float*)d_in[5];
    const float* b      = (const float*)d_in[6];
    const float* W_out  = (const float*)d_in[7];
    const float* b_out  = (const float*)d_in[8];
    float* out = (float*)d_out;

    cudaFuncSetAttribute(lstm_main, cudaFuncAttributeMaxDynamicSharedMemorySize,
                         SMEM_BYTES);

    repack_kernel<<<(2 * 8 * NK * 128 + 255) / 256, 256>>>(W_ih, W_hh, W_out);
    bias_kernel<<<8, 256>>>(W_ih, b, b_out);
    lstm_main<<<NCTA, THREADS, SMEM_BYTES>>>(c0, h0, warm, autoin,
                                             W_out, b_out, out);
}

// round 17
// speedup vs baseline: 1.4216x; 1.4216x over previous
#include <cuda_runtime.h>

// FullAutoLSTM, GB300 sm_103a.
// 128 independent CTAs x 256 threads. Thread t = hidden unit u (all 4 gates,
// all 8 batch rows of its CTA). Weights gate-interleaved, streamed from L2
// with an explicit 2-block register prefetch pipeline (hides ~240cyc L2 hit
// latency under FFMA2 work). x tile duplicated {x,x} in smem, 80B k-stride,
// so 8 rows = 4 broadcast LDS.128. c in registers; h + y feedback CTA-local.
// fp32 GEMM via packed fma.rn.f32x2.

typedef unsigned long long ull;

#define TW   512
#define TA   512
#define TT   1024
#define NB   1024
#define NH   256
#define NF   32     // 24 auto features + 8 recurrent y
#define FA   24
#define NO   8
#define NK   288    // NF + NH
#define BT   8      // batch rows per CTA
#define NCTA (NB / BT)   // 128
#define THREADS 256
#define XS   20     // x-tile k-stride in floats (16 data + 4 pad = 80B)

// Gate-interleaved weights: g_Wr[k*1024 + u*4 + g], g = 0:i 1:f 2:g 3:o,
// source column = g*256 + u. One ulonglong2 per (k,u) = {wi,wf},{wg,wo}.
// Padded by 16 k-rows: the prefetch pipeline harmlessly over-reads one block.
__device__ float g_Wr[(NK + 16) * 4 * NH];

__device__ __forceinline__ void fma2(ull& a, ull x, ull w) {
    asm("fma.rn.f32x2 %0, %1, %2, %0;" : "+l"(a) : "l"(x), "l"(w));
}
__device__ __forceinline__ float2 unp(ull v) {
    float2 r; asm("mov.b64 {%0, %1}, %2;" : "=f"(r.x), "=f"(r.y) : "l"(v)); return r;
}
__device__ __forceinline__ float fsig(float x) { return 1.0f / (1.0f + __expf(-x)); }
__device__ __forceinline__ float fth(float x)  { return 2.0f / (1.0f + __expf(-2.0f * x)) - 1.0f; }

__global__ void repack_kernel(const float* __restrict__ W_ih,
                              const float* __restrict__ W_hh) {
    int i = blockIdx.x * blockDim.x + threadIdx.x;
    if (i >= (NK + 16) * 4 * NH) return;
    int k = i >> 10;
    int c = i & 1023;
    int u = c >> 2;
    int g = c & 3;
    int col = g * NH + u;
    float v = 0.0f;
    if (k < NF)       v = W_ih[(size_t)k * (4 * NH) + col];
    else if (k < NK)  v = W_hh[(size_t)(k - NF) * (4 * NH) + col];
    g_Wr[i] = v;   // pad rows [NK, NK+16) stay zero
}

// One k-step of the GEMM: 4 broadcast LDS.128 + 16 packed FFMA2.
__device__ __forceinline__ void consume_k(const float* __restrict__ sx, int k,
                                          ulonglong2 w2, ull* aif, ull* ago) {
    const ulonglong2* xk = (const ulonglong2*)&sx[k * XS];
    ulonglong2 x01 = xk[0];   // {x_r0 dup, x_r1 dup}
    ulonglong2 x23 = xk[1];
    ulonglong2 x45 = xk[2];
    ulonglong2 x67 = xk[3];
    fma2(aif[0], x01.x, w2.x); fma2(ago[0], x01.x, w2.y);
    fma2(aif[1], x01.y, w2.x); fma2(ago[1], x01.y, w2.y);
    fma2(aif[2], x23.x, w2.x); fma2(ago[2], x23.x, w2.y);
    fma2(aif[3], x23.y, w2.x); fma2(ago[3], x23.y, w2.y);
    fma2(aif[4], x45.x, w2.x); fma2(ago[4], x45.x, w2.y);
    fma2(aif[5], x45.y, w2.x); fma2(ago[5], x45.y, w2.y);
    fma2(aif[6], x67.x, w2.x); fma2(ago[6], x67.x, w2.y);
    fma2(aif[7], x67.y, w2.x); fma2(ago[7], x67.y, w2.y);
}

__global__ void __launch_bounds__(THREADS, 1)
lstm_main(const float* __restrict__ c0, const float* __restrict__ h0,
          const float* __restrict__ warm,    // (B, TW, 32)
          const float* __restrict__ autoin,  // (B, TA, 24)
          const float* __restrict__ bias,    // (1024)
          const float* __restrict__ W_out,   // (256, 8)
          const float* __restrict__ b_out,   // (8)
          float* __restrict__ out)           // (B, TT, 8)
{
    // x tile: sx[k*XS + 2r] = {x_rk, x_rk}. 80B per k row (16B-aligned).
    // k in [0,FA): auto feats; [FA,NF): warm feats / y feedback; [NF,NK): h.
    __shared__ float sx[NK * XS];        // 23040 B
    __shared__ float swout[NH * NO];     //  8192 B
    __shared__ float psum[BT * NO][5];   //  1280 B

    const int t  = threadIdx.x;          // == hidden unit u
    const int b0 = blockIdx.x * BT;

    for (int i = t; i < NH * NO; i += THREADS) swout[i] = W_out[i];
    const float bi = bias[t],           bf = bias[NH + t];
    const float bg = bias[2 * NH + t],  bo = bias[3 * NH + t];
    const float bor = b_out[t & 7];

    float cr[BT];
#pragma unroll
    for (int r = 0; r < BT; r++) {
        cr[r] = c0[(size_t)(b0 + r) * NH + t];
        float v = h0[(size_t)(b0 + r) * NH + t];
        *(float2*)&sx[(NF + t) * XS + 2 * r] = make_float2(v, v);
    }

    const ulonglong2* __restrict__ wp =
        reinterpret_cast<const ulonglong2*>(g_Wr) + t;   // +k*256 per k

    for (int s = 0; s < TT; s++) {
        // ---- stage x_s ----
        if (s < TW) {
            int r = t >> 5, k = t & 31;
            float v = warm[((size_t)(b0 + r) * TW + s) * NF + k];
            *(float2*)&sx[k * XS + 2 * r] = make_float2(v, v);
        } else if (t < FA * BT) {
            int r = t / FA, k = t - r * FA;
            float v = autoin[((size_t)(b0 + r) * TA + (s - TW)) * FA + k];
            *(float2*)&sx[k * XS + 2 * r] = make_float2(v, v);
        }
        __syncthreads();  // S1: x staged; h + y feedback visible

        // ---- z GEMM with 2-block register prefetch (8 k per block) ----
        ull aif[BT], ago[BT];
#pragma unroll
        for (int r = 0; r < BT; r++) { aif[r] = 0ULL; ago[r] = 0ULL; }

        ulonglong2 wA[8], wB[8];
#pragma unroll
        for (int j = 0; j < 8; j++)
            wA[j] = __ldg(&wp[(size_t)j * 256]);

#pragma unroll 1
        for (int kb = 0; kb < NK; kb += 16) {
#pragma unroll
            for (int j = 0; j < 8; j++)
                wB[j] = __ldg(&wp[(size_t)(kb + 8 + j) * 256]);
#pragma unroll
            for (int j = 0; j < 8; j++)
                consume_k(sx, kb + j, wA[j], aif, ago);
#pragma unroll
            for (int j = 0; j < 8; j++)  // last iter over-reads into zero pad
                wA[j] = __ldg(&wp[(size_t)(kb + 16 + j) * 256]);
#pragma unroll
            for (int j = 0; j < 8; j++)
                consume_k(sx, kb + 8 + j, wB[j], aif, ago);
        }

        // ---- gates + cell update (c in registers) ----
        float hv[BT];
#pragma unroll
        for (int r = 0; r < BT; r++) {
            float2 zif = unp(aif[r]);
            float2 zgo = unp(ago[r]);
            float ig = fsig(zif.x + bi);
            float fg = fsig(zif.y + bf);
            float gg = fth(zgo.x + bg);
            float og = fsig(zgo.y + bo);
            float c  = fmaf(fg, cr[r], ig * gg);
            cr[r] = c;
            hv[r] = og * fth(c);
        }
        __syncthreads();  // S2: all GEMM smem reads complete

        // h_s -> sx (4 STS.128)
#pragma unroll
        for (int rp = 0; rp < 4; rp++) {
            *(float4*)&sx[(NF + t) * XS + 4 * rp] =
                make_float4(hv[2 * rp], hv[2 * rp], hv[2 * rp + 1], hv[2 * rp + 1]);
        }
        __syncthreads();  // S3: h_s visible

        // ---- y_s = h_s @ W_out + b_out: 4 partial chunks of 64 units ----
        {
            int combo = t & 63;           // (r, o)
            int p = t >> 6;               // 0..3 -> unit chunk of 64
            int r = combo >> 3, o = combo & 7;
            float a0 = 0.f, a1 = 0.f;
#pragma unroll 8
            for (int jj = 0; jj < 64; jj += 2) {
                int j = 64 * p + jj;
                a0 = fmaf(sx[(NF + j) * XS + 2 * r],     swout[j * NO + o],       a0);
                a1 = fmaf(sx[(NF + j + 1) * XS + 2 * r], swout[(j + 1) * NO + o], a1);
            }
            psum[combo][p] = a0 + a1;
        }
        __syncthreads();  // S4: partials visible

        if (t < BT * NO) {
            int r = t >> 3, o = t & 7;
            float y = bor + ((psum[t][0] + psum[t][1]) +
                             (psum[t][2] + psum[t][3]));
            out[((size_t)(b0 + r) * TT + s) * NO + o] = y;
            // Autoregressive feedback into next step's input slots [24,32).
            if (s >= TW - 1 && s < TT - 1)
                *(float2*)&sx[(FA + o) * XS + 2 * r] = make_float2(y, y);
        }
    }
}

extern "C" void kernel_launch(void* const* d_in, const int* in_sizes, int n_in,
                              void* d_out, int out_size) {
    const float* c0     = (const float*)d_in[0];
    const float* h0     = (const float*)d_in[1];
    const float* warm   = (const float*)d_in[2];
    const float* autoin = (const float*)d_in[3];
    const float* W_ih   = (const float*)d_in[4];
    const float* W_hh   = (const float*)d_in[5];
    const float* bias   = (const float*)d_in[6];
    const float* W_out  = (const float*)d_in[7];
    const float* b_out  = (const float*)d_in[8];
    float* out = (float*)d_out;

    repack_kernel<<<((NK + 16) * 4 * NH + 255) / 256, 256>>>(W_ih, W_hh);
    lstm_main<<<NCTA, THREADS>>>(c0, h0, warm, autoin, bias, W_out, b_out, out);
}